// round 5
// baseline (speedup 1.0000x reference)
#include <cuda_runtime.h>

#define G    8
#define CG   32
#define CH   256
#define HWP  16384                 // H*W
#define TPB  128

typedef unsigned long long ull;

__device__ __forceinline__ ull pack2(float a, float b) {
    ull r; asm("mov.b64 %0, {%1,%2};" : "=l"(r) : "f"(a), "f"(b)); return r;
}
__device__ __forceinline__ void unpack2(ull v, float& a, float& b) {
    asm("mov.b64 {%0,%1}, %2;" : "=f"(a), "=f"(b) : "l"(v));
}
__device__ __forceinline__ void fma2(ull& d, ull a, ull b) {
    asm("fma.rn.f32x2 %0, %1, %2, %0;" : "+l"(d) : "l"(a), "l"(b));
}

#define NEG_INF __int_as_float(0xff800000)

__global__ void __launch_bounds__(TPB, 3)
cgblock_kernel(const float* __restrict__ x,
               const float* __restrict__ soft_w1,
               const float* __restrict__ soft_w2,
               const float* __restrict__ top_w1,
               const float* __restrict__ top_w2,
               const float* __restrict__ rr,
               float* __restrict__ out)
{
    __shared__ __align__(16) ull s_w2[CH * 16];   // packed (w,w): j<8 soft, j>=8 top
    __shared__ float s_w1[G * CG];
    __shared__ float s_tw1[G * 4];

    const int tid = threadIdx.x;

    // branch-mix softmax, folded into w2
    float r0 = __ldg(rr), r1 = __ldg(rr + 1);
    float rm = fmaxf(r0, r1);
    float er0 = __expf(r0 - rm), er1 = __expf(r1 - rm);
    float rinv = __frcp_rn(er0 + er1);
    float w_top = er0 * rinv, w_soft = er1 * rinv;

    #pragma unroll 8
    for (int i = tid; i < CH * 16; i += TPB) {
        int o = i >> 4, j = i & 15;
        float w = (j < 8) ? (w_soft * __ldg(soft_w2 + o * G + j))
                          : (w_top  * __ldg(top_w2  + o * G + (j - 8)));
        s_w2[i] = pack2(w, w);
    }
    #pragma unroll
    for (int i = tid; i < G * CG; i += TPB) s_w1[i] = __ldg(soft_w1 + i);
    if (tid < G * 4) s_tw1[tid] = __ldg(top_w1 + tid);
    __syncthreads();

    // one float4 quad of pixels per thread, coalesced across the warp
    int q  = blockIdx.x * TPB + tid;
    int p  = q << 2;
    int b  = p >> 14;
    int sp = p & (HWP - 1);
    const float* xb = x   + (size_t)b * CH * HWP + sp;
    float*       ob = out + (size_t)b * CH * HWP + sp;

    // branch outputs packed by pixel pair: sA = px(0,1), sB = px(2,3); j<8 sv, j>=8 tv
    ull sA[16], sB[16];

    // ---------------- Phase 1: pipelined, batches of 4 channels (float4 loads) ----
    float4 cur[4], nxt[4];
    #pragma unroll
    for (int i = 0; i < 4; i++) cur[i] = *(const float4*)(xb + (size_t)i * HWP);

    #pragma unroll
    for (int g = 0; g < G; g++) {
        float es[4] = {0.f, 0.f, 0.f, 0.f};
        float ys[4] = {0.f, 0.f, 0.f, 0.f};
        float ta[4], tb[4], tc[4], td[4];
        #pragma unroll
        for (int px = 0; px < 4; px++) { ta[px] = tb[px] = tc[px] = td[px] = NEG_INF; }

        #pragma unroll
        for (int bt = 0; bt < 8; bt++) {
            int nc = g * CG + (bt + 1) * 4;          // next batch's first channel
            if (nc < CH) {
                #pragma unroll
                for (int i = 0; i < 4; i++)
                    nxt[i] = *(const float4*)(xb + (size_t)(nc + i) * HWP);
            }
            #pragma unroll
            for (int i = 0; i < 4; i++) {
                float w1 = s_w1[g * CG + bt * 4 + i];
                float vv[4] = {cur[i].x, cur[i].y, cur[i].z, cur[i].w};
                #pragma unroll
                for (int px = 0; px < 4; px++) {
                    float v = vv[px];
                    float e = __expf(v);
                    es[px] += e;
                    ys[px]  = fmaf(v * e, w1, ys[px]);
                    float f  = fminf(ta[px], v); ta[px] = fmaxf(ta[px], v);
                    float h  = fminf(tb[px], f); tb[px] = fmaxf(tb[px], f);
                    float i2 = fminf(tc[px], h); tc[px] = fmaxf(tc[px], h);
                    td[px] = fmaxf(td[px], i2);
                }
            }
            #pragma unroll
            for (int i = 0; i < 4; i++) cur[i] = nxt[i];
        }

        float k0 = s_tw1[g * 4 + 0], k1 = s_tw1[g * 4 + 1];
        float k2 = s_tw1[g * 4 + 2], k3 = s_tw1[g * 4 + 3];
        float sv[4], tv[4];
        #pragma unroll
        for (int px = 0; px < 4; px++) {
            sv[px] = __fdividef(ys[px], es[px]);
            tv[px] = fmaf(ta[px], k0, fmaf(tb[px], k1, fmaf(tc[px], k2, td[px] * k3)));
        }
        sA[g]     = pack2(sv[0], sv[1]);
        sB[g]     = pack2(sv[2], sv[3]);
        sA[8 + g] = pack2(tv[0], tv[1]);
        sB[8 + g] = pack2(tv[2], tv[3]);
    }

    // ---------------- Phase 2: reverse channels, pipelined batches of 4 ----------
    float4 c4[4], n4[4];
    #pragma unroll
    for (int i = 0; i < 4; i++)
        c4[i] = *(const float4*)(xb + (size_t)(CH - 1 - i) * HWP);

    #pragma unroll 2
    for (int ob2 = 0; ob2 < CH / 4; ob2++) {
        if (ob2 < CH / 4 - 1) {
            int nc = CH - 1 - (ob2 + 1) * 4;
            #pragma unroll
            for (int i = 0; i < 4; i++)
                n4[i] = *(const float4*)(xb + (size_t)(nc - i) * HWP);
        }
        #pragma unroll
        for (int i = 0; i < 4; i++) {
            int o = CH - 1 - ob2 * 4 - i;
            ull acc01 = pack2(c4[i].x, c4[i].y);
            ull acc23 = pack2(c4[i].z, c4[i].w);
            const ulonglong2* wp = (const ulonglong2*)(s_w2 + (o << 4));
            #pragma unroll
            for (int jj = 0; jj < 8; jj++) {
                ulonglong2 wv = wp[jj];
                fma2(acc01, sA[2 * jj],     wv.x);
                fma2(acc23, sB[2 * jj],     wv.x);
                fma2(acc01, sA[2 * jj + 1], wv.y);
                fma2(acc23, sB[2 * jj + 1], wv.y);
            }
            float4 ov;
            unpack2(acc01, ov.x, ov.y);
            unpack2(acc23, ov.z, ov.w);
            __stcs((float4*)(ob + (size_t)o * HWP), ov);
        }
        #pragma unroll
        for (int i = 0; i < 4; i++) c4[i] = n4[i];
    }
}

extern "C" void kernel_launch(void* const* d_in, const int* in_sizes, int n_in,
                              void* d_out, int out_size) {
    const float* x   = (const float*)d_in[0];
    const float* sw1 = (const float*)d_in[1];
    const float* sw2 = (const float*)d_in[2];
    const float* tw1 = (const float*)d_in[3];
    const float* tw2 = (const float*)d_in[4];
    const float* r   = (const float*)d_in[5];
    float* out = (float*)d_out;

    int pixels = out_size / CH;        // 262144
    int quads  = pixels >> 2;          // 65536
    int blocks = quads / TPB;          // 512

    cgblock_kernel<<<blocks, TPB>>>(x, sw1, sw2, tw1, tw2, r, out);
}

// round 6
// speedup vs baseline: 1.7772x; 1.7772x over previous
#include <cuda_runtime.h>
#include <cstdint>

#define G    8
#define CG   32
#define CH   256
#define HWP  16384
#define TPB  256
#define PT   64            // pixels per tile
#define XS   72            // padded smem row stride in floats (288B)
#define NT   4096          // 262144 / PT

typedef unsigned long long ull;

__device__ __forceinline__ ull pack2(float a, float b) {
    ull r; asm("mov.b64 %0, {%1,%2};" : "=l"(r) : "f"(a), "f"(b)); return r;
}
__device__ __forceinline__ void unpack2(ull v, float& a, float& b) {
    asm("mov.b64 {%0,%1}, %2;" : "=f"(a), "=f"(b) : "l"(v));
}
__device__ __forceinline__ void fma2(ull& d, ull a, ull b) {
    asm("fma.rn.f32x2 %0, %1, %2, %0;" : "+l"(d) : "l"(a), "l"(b));
}
__device__ __forceinline__ uint32_t smem_u32(const void* p) {
    uint32_t a;
    asm("{ .reg .u64 t; cvta.to.shared.u64 t, %1; cvt.u32.u64 %0, t; }" : "=r"(a) : "l"(p));
    return a;
}
__device__ __forceinline__ void cpa16(uint32_t dst, const float* src) {
    asm volatile("cp.async.cg.shared.global [%0], [%1], 16;" :: "r"(dst), "l"(src));
}

#define NEG_INF __int_as_float(0xff800000)

// smem float-offsets
#define OFF_X0    0
#define OFF_X1    (CH * XS)                 // 18432
#define OFF_W2    (2 * CH * XS)             // 36864  (ull[CH*16] = 8192 floats)
#define OFF_ST    (OFF_W2 + CH * 16 * 2)    // 45056  (stats 16*64)
#define OFF_W1    (OFF_ST + 16 * PT)        // 46080
#define OFF_TW1   (OFF_W1 + G * CG)         // 46336
#define SMEM_FLTS (OFF_TW1 + G * 4)         // 46368 floats = 185472 B

__global__ void __launch_bounds__(TPB, 1)
cgblock_kernel(const float* __restrict__ x,
               const float* __restrict__ soft_w1,
               const float* __restrict__ soft_w2,
               const float* __restrict__ top_w1,
               const float* __restrict__ top_w2,
               const float* __restrict__ rr,
               float* __restrict__ out)
{
    extern __shared__ float sm[];
    ull*   s_w2   = (ull*)(sm + OFF_W2);
    float* s_st   = sm + OFF_ST;
    float* s_w1   = sm + OFF_W1;
    float* s_tw1  = sm + OFF_TW1;

    const int tid  = threadIdx.x;
    const int warp = tid >> 5;
    const int lane = tid & 31;

    // ---- one-time weight prep ----
    {
        float r0 = __ldg(rr), r1 = __ldg(rr + 1);
        float rm = fmaxf(r0, r1);
        float e0 = __expf(r0 - rm), e1 = __expf(r1 - rm);
        float inv = __frcp_rn(e0 + e1);
        float w_top = e0 * inv, w_soft = e1 * inv;
        #pragma unroll
        for (int i = tid; i < CH * 16; i += TPB) {
            int o = i >> 4, j = i & 15;
            float w = (j < 8) ? (w_soft * __ldg(soft_w2 + o * G + j))
                              : (w_top  * __ldg(top_w2  + o * G + (j - 8)));
            s_w2[i] = pack2(w, w);
        }
        if (tid < G * CG) s_w1[tid] = __ldg(soft_w1 + tid);
        if (tid < G * 4)  s_tw1[tid] = __ldg(top_w1 + tid);
    }
    __syncthreads();

    const uint32_t xb_u32[2] = { smem_u32(sm + OFF_X0), smem_u32(sm + OFF_X1) };

    // ---- prologue: load first tile into buffer 0 ----
    int t0 = blockIdx.x;
    {
        int p = t0 * PT, b = p >> 14, sp = p & (HWP - 1);
        const float* src = x + ((size_t)b * CH + tid) * HWP + sp;   // tid = channel
        uint32_t dst = xb_u32[0] + tid * (XS * 4);
        #pragma unroll
        for (int j = 0; j < 16; j++) cpa16(dst + j * 16, src + j * 4);
        asm volatile("cp.async.commit_group;" ::: "memory");
    }

    int k = 0;
    for (int t = t0; t < NT; t += gridDim.x, k ^= 1) {
        int tn = t + gridDim.x;
        // issue next tile into the other buffer (freed by last iter's final barrier)
        if (tn < NT) {
            int p = tn * PT, b = p >> 14, sp = p & (HWP - 1);
            const float* src = x + ((size_t)b * CH + tid) * HWP + sp;
            uint32_t dst = xb_u32[k ^ 1] + tid * (XS * 4);
            #pragma unroll
            for (int j = 0; j < 16; j++) cpa16(dst + j * 16, src + j * 4);
            asm volatile("cp.async.commit_group;" ::: "memory");
            asm volatile("cp.async.wait_group 1;" ::: "memory");
        } else {
            asm volatile("cp.async.wait_group 0;" ::: "memory");
        }
        __syncthreads();   // current tile visible to all threads

        const float* xt = sm + (k ? OFF_X1 : OFF_X0);
        const int p  = t * PT;
        const int b  = p >> 14;
        const int sp = p & (HWP - 1);

        // ---------------- Phase 1: stats. thread = (group=warp, pixel-pair=lane) ----
        {
            const int g = warp, pr = lane;
            const float* xrow = xt + (g * CG) * XS + pr * 2;
            float es0 = 0.f, es1 = 0.f, ys0 = 0.f, ys1 = 0.f;
            float a0 = NEG_INF, b0 = NEG_INF, c0 = NEG_INF, d0 = NEG_INF;
            float a1 = NEG_INF, b1 = NEG_INF, c1 = NEG_INF, d1 = NEG_INF;
            #pragma unroll 8
            for (int c = 0; c < CG; c++) {
                float2 v = *(const float2*)(xrow + c * XS);
                float w1 = s_w1[g * CG + c];
                {
                    float e = __expf(v.x); es0 += e; ys0 = fmaf(v.x * e, w1, ys0);
                    float f  = fminf(a0, v.x); a0 = fmaxf(a0, v.x);
                    float h  = fminf(b0, f);   b0 = fmaxf(b0, f);
                    float i2 = fminf(c0, h);   c0 = fmaxf(c0, h);
                    d0 = fmaxf(d0, i2);
                }
                {
                    float e = __expf(v.y); es1 += e; ys1 = fmaf(v.y * e, w1, ys1);
                    float f  = fminf(a1, v.y); a1 = fmaxf(a1, v.y);
                    float h  = fminf(b1, f);   b1 = fmaxf(b1, f);
                    float i2 = fminf(c1, h);   c1 = fmaxf(c1, h);
                    d1 = fmaxf(d1, i2);
                }
            }
            float k0 = s_tw1[g * 4 + 0], k1 = s_tw1[g * 4 + 1];
            float k2 = s_tw1[g * 4 + 2], k3 = s_tw1[g * 4 + 3];
            *(float2*)(s_st + g * PT + 2 * pr) =
                make_float2(__fdividef(ys0, es0), __fdividef(ys1, es1));
            *(float2*)(s_st + (8 + g) * PT + 2 * pr) =
                make_float2(fmaf(a0, k0, fmaf(b0, k1, fmaf(c0, k2, d0 * k3))),
                            fmaf(a1, k0, fmaf(b1, k1, fmaf(c1, k2, d1 * k3))));
        }
        __syncthreads();   // stats ready

        // ---------------- Phase 2: thread = (warp-> 32 chans, half -> chan parity, qd -> pixel quad)
        {
            const int half = lane >> 4, qd = lane & 15;
            ull sA[16], sB[16];
            #pragma unroll
            for (int j = 0; j < 16; j++) {
                float4 s4 = *(const float4*)(s_st + j * PT + qd * 4);
                sA[j] = pack2(s4.x, s4.y);
                sB[j] = pack2(s4.z, s4.w);
            }
            float* ob = out + (size_t)b * CH * HWP + sp + qd * 4;
            #pragma unroll 2
            for (int i = 0; i < 16; i++) {
                int o = warp * 32 + i * 2 + half;
                float4 xv = *(const float4*)(xt + o * XS + qd * 4);
                ull acc01 = pack2(xv.x, xv.y);
                ull acc23 = pack2(xv.z, xv.w);
                const ulonglong2* wp = (const ulonglong2*)(s_w2 + (o << 4));
                #pragma unroll
                for (int jj = 0; jj < 8; jj++) {
                    ulonglong2 wv = wp[jj];
                    fma2(acc01, sA[2 * jj],     wv.x);
                    fma2(acc23, sB[2 * jj],     wv.x);
                    fma2(acc01, sA[2 * jj + 1], wv.y);
                    fma2(acc23, sB[2 * jj + 1], wv.y);
                }
                float4 ov;
                unpack2(acc01, ov.x, ov.y);
                unpack2(acc23, ov.z, ov.w);
                __stcs((float4*)(ob + (size_t)o * HWP), ov);
            }
        }
        __syncthreads();   // frees this buffer for the next prefetch
    }
}

extern "C" void kernel_launch(void* const* d_in, const int* in_sizes, int n_in,
                              void* d_out, int out_size) {
    const float* x   = (const float*)d_in[0];
    const float* sw1 = (const float*)d_in[1];
    const float* sw2 = (const float*)d_in[2];
    const float* tw1 = (const float*)d_in[3];
    const float* tw2 = (const float*)d_in[4];
    const float* r   = (const float*)d_in[5];
    float* out = (float*)d_out;

    static int sms = 0;
    if (sms == 0) cudaDeviceGetAttribute(&sms, cudaDevAttrMultiProcessorCount, 0);

    const int smem_bytes = SMEM_FLTS * 4;   // 185472
    static bool attr_set = false;
    if (!attr_set) {
        cudaFuncSetAttribute(cgblock_kernel,
                             cudaFuncAttributeMaxDynamicSharedMemorySize, smem_bytes);
        attr_set = true;
    }

    cgblock_kernel<<<sms, TPB, smem_bytes>>>(x, sw1, sw2, tw1, tw2, r, out);
}

// round 7
// speedup vs baseline: 2.0197x; 1.1365x over previous
#include <cuda_runtime.h>
#include <cstdint>

#define G    8
#define CG   32
#define CH   256
#define HWP  16384
#define TPB  512
#define PT   64            // pixels per tile
#define XS   72            // padded smem row stride in floats (288B)
#define NT   4096          // 262144 / PT

typedef unsigned long long ull;

__device__ __forceinline__ ull pack2(float a, float b) {
    ull r; asm("mov.b64 %0, {%1,%2};" : "=l"(r) : "f"(a), "f"(b)); return r;
}
__device__ __forceinline__ void unpack2(ull v, float& a, float& b) {
    asm("mov.b64 {%0,%1}, %2;" : "=f"(a), "=f"(b) : "l"(v));
}
__device__ __forceinline__ void fma2(ull& d, ull a, ull b) {
    asm("fma.rn.f32x2 %0, %1, %2, %0;" : "+l"(d) : "l"(a), "l"(b));
}
__device__ __forceinline__ uint32_t smem_u32(const void* p) {
    uint32_t a;
    asm("{ .reg .u64 t; cvta.to.shared.u64 t, %1; cvt.u32.u64 %0, t; }" : "=r"(a) : "l"(p));
    return a;
}
__device__ __forceinline__ void cpa16(uint32_t dst, const float* src) {
    asm volatile("cp.async.cg.shared.global [%0], [%1], 16;" :: "r"(dst), "l"(src));
}

#define NEG_INF __int_as_float(0xff800000)

// smem float-offsets
#define OFF_X0    0
#define OFF_X1    (CH * XS)                 // 18432
#define OFF_W2    (2 * CH * XS)             // 36864  (ull[CH*16] = 8192 floats)
#define OFF_ST    (OFF_W2 + CH * 16 * 2)    // 45056  (stats 16*64)
#define OFF_W1    (OFF_ST + 16 * PT)        // 46080
#define OFF_TW1   (OFF_W1 + G * CG)         // 46336
#define SMEM_FLTS (OFF_TW1 + G * 4)         // 46368 floats = 185472 B

__global__ void __launch_bounds__(TPB, 1)
cgblock_kernel(const float* __restrict__ x,
               const float* __restrict__ soft_w1,
               const float* __restrict__ soft_w2,
               const float* __restrict__ top_w1,
               const float* __restrict__ top_w2,
               const float* __restrict__ rr,
               float* __restrict__ out)
{
    extern __shared__ float sm[];
    ull*   s_w2  = (ull*)(sm + OFF_W2);
    float* s_st  = sm + OFF_ST;
    float* s_w1  = sm + OFF_W1;
    float* s_tw1 = sm + OFF_TW1;

    const int tid  = threadIdx.x;
    const int warp = tid >> 5;
    const int lane = tid & 31;

    // ---- one-time weight prep ----
    {
        float r0 = __ldg(rr), r1 = __ldg(rr + 1);
        float rm = fmaxf(r0, r1);
        float e0 = __expf(r0 - rm), e1 = __expf(r1 - rm);
        float inv = __frcp_rn(e0 + e1);
        float w_top = e0 * inv, w_soft = e1 * inv;
        #pragma unroll
        for (int i = tid; i < CH * 16; i += TPB) {
            int o = i >> 4, j = i & 15;
            float w = (j < 8) ? (w_soft * __ldg(soft_w2 + o * G + j))
                              : (w_top  * __ldg(top_w2  + o * G + (j - 8)));
            s_w2[i] = pack2(w, w);
        }
        if (tid < G * CG) s_w1[tid] = __ldg(soft_w1 + tid);
        if (tid < G * 4)  s_tw1[tid] = __ldg(top_w1 + tid);
    }
    __syncthreads();

    const uint32_t xb_u32[2] = { smem_u32(sm + OFF_X0), smem_u32(sm + OFF_X1) };

    // prefetch mapping: each warp covers 2 whole channel rows contiguously.
    const int ld_ch0   = tid >> 4;      // 0..31 (channel within 32-chan slab)
    const int ld_chunk = tid & 15;      // 16B chunk within 64-px row

    // ---- prologue: load first tile into buffer 0 ----
    int t0 = blockIdx.x;
    {
        int p = t0 * PT, b = p >> 14, sp = p & (HWP - 1);
        #pragma unroll
        for (int cc = 0; cc < 8; cc++) {
            int ch = cc * 32 + ld_ch0;
            cpa16(xb_u32[0] + (ch * XS + ld_chunk * 4) * 4,
                  x + ((size_t)b * CH + ch) * HWP + sp + ld_chunk * 4);
        }
        asm volatile("cp.async.commit_group;" ::: "memory");
    }

    int k = 0;
    for (int t = t0; t < NT; t += gridDim.x, k ^= 1) {
        int tn = t + gridDim.x;
        if (tn < NT) {
            int p = tn * PT, b = p >> 14, sp = p & (HWP - 1);
            #pragma unroll
            for (int cc = 0; cc < 8; cc++) {
                int ch = cc * 32 + ld_ch0;
                cpa16(xb_u32[k ^ 1] + (ch * XS + ld_chunk * 4) * 4,
                      x + ((size_t)b * CH + ch) * HWP + sp + ld_chunk * 4);
            }
            asm volatile("cp.async.commit_group;" ::: "memory");
            asm volatile("cp.async.wait_group 1;" ::: "memory");
        } else {
            asm volatile("cp.async.wait_group 0;" ::: "memory");
        }
        __syncthreads();   // current tile visible

        const float* xt = sm + (k ? OFF_X1 : OFF_X0);
        const int p  = t * PT;
        const int b  = p >> 14;
        const int sp = p & (HWP - 1);

        // ---------- Phase 1: thread = (group, single pixel). 512-way. ----------
        {
            const int g  = tid >> 6;      // 0..7
            const int px = tid & 63;      // 0..63
            const float* xrow = xt + (g * CG) * XS + px;
            float es = 0.f, ys = 0.f;
            float a0 = NEG_INF, b0 = NEG_INF, c0 = NEG_INF, d0 = NEG_INF;
            #pragma unroll 8
            for (int c = 0; c < CG; c++) {
                float v  = xrow[c * XS];
                float w1 = s_w1[g * CG + c];
                float e = __expf(v); es += e; ys = fmaf(v * e, w1, ys);
                float f  = fminf(a0, v); a0 = fmaxf(a0, v);
                float h  = fminf(b0, f); b0 = fmaxf(b0, f);
                float i2 = fminf(c0, h); c0 = fmaxf(c0, h);
                d0 = fmaxf(d0, i2);
            }
            float k0 = s_tw1[g * 4 + 0], k1 = s_tw1[g * 4 + 1];
            float k2 = s_tw1[g * 4 + 2], k3 = s_tw1[g * 4 + 3];
            s_st[g * PT + px]       = __fdividef(ys, es);
            s_st[(8 + g) * PT + px] = fmaf(a0, k0, fmaf(b0, k1, fmaf(c0, k2, d0 * k3)));
        }
        __syncthreads();   // stats ready

        // ---------- Phase 2: thread = (16 channels, pixel pair). ----------
        {
            const int pp = lane;              // pixel pair 0..31
            ull sA[16];
            #pragma unroll
            for (int j = 0; j < 16; j++) {
                float2 s2 = *(const float2*)(s_st + j * PT + 2 * pp);
                sA[j] = pack2(s2.x, s2.y);
            }
            float* ob = out + (size_t)b * CH * HWP + sp + 2 * pp;
            #pragma unroll 4
            for (int i = 0; i < 16; i++) {
                int o = warp * 16 + i;
                float2 xv = *(const float2*)(xt + o * XS + 2 * pp);
                ull acc = pack2(xv.x, xv.y);
                const ulonglong2* wp = (const ulonglong2*)(s_w2 + (o << 4));
                #pragma unroll
                for (int jj = 0; jj < 8; jj++) {
                    ulonglong2 wv = wp[jj];
                    fma2(acc, sA[2 * jj],     wv.x);
                    fma2(acc, sA[2 * jj + 1], wv.y);
                }
                float2 ov;
                unpack2(acc, ov.x, ov.y);
                __stcs((float2*)(ob + (size_t)o * HWP), ov);
            }
        }
        __syncthreads();   // frees this buffer for next prefetch
    }
}

extern "C" void kernel_launch(void* const* d_in, const int* in_sizes, int n_in,
                              void* d_out, int out_size) {
    const float* x   = (const float*)d_in[0];
    const float* sw1 = (const float*)d_in[1];
    const float* sw2 = (const float*)d_in[2];
    const float* tw1 = (const float*)d_in[3];
    const float* tw2 = (const float*)d_in[4];
    const float* r   = (const float*)d_in[5];
    float* out = (float*)d_out;

    static int sms = 0;
    if (sms == 0) cudaDeviceGetAttribute(&sms, cudaDevAttrMultiProcessorCount, 0);

    const int smem_bytes = SMEM_FLTS * 4;   // 185472
    static bool attr_set = false;
    if (!attr_set) {
        cudaFuncSetAttribute(cgblock_kernel,
                             cudaFuncAttributeMaxDynamicSharedMemorySize, smem_bytes);
        attr_set = true;
    }

    cgblock_kernel<<<sms, TPB, smem_bytes>>>(x, sw1, sw2, tw1, tw2, r, out);
}

// round 8
// speedup vs baseline: 2.4329x; 1.2046x over previous
#include <cuda_runtime.h>
#include <cstdint>

#define G    8
#define CG   32
#define CH   256
#define HWP  16384
#define TPB  512
#define PT   64
#define NT   4096
#define SROW 9                      // stats stride per pixel, in ull

typedef unsigned long long ull;

__device__ __forceinline__ ull pack2(float a, float b) {
    ull r; asm("mov.b64 %0, {%1,%2};" : "=l"(r) : "f"(a), "f"(b)); return r;
}
__device__ __forceinline__ void unpack2(ull v, float& a, float& b) {
    asm("mov.b64 {%0,%1}, %2;" : "=f"(a), "=f"(b) : "l"(v));
}
__device__ __forceinline__ void fma2(ull& d, ull a, ull b) {
    asm("fma.rn.f32x2 %0, %1, %2, %0;" : "+l"(d) : "l"(a), "l"(b));
}
__device__ __forceinline__ uint32_t smem_u32(const void* p) {
    uint32_t a;
    asm("{ .reg .u64 t; cvta.to.shared.u64 t, %1; cvt.u32.u64 %0, t; }" : "=r"(a) : "l"(p));
    return a;
}
__device__ __forceinline__ void cpa16(uint32_t dst, const float* src) {
    asm volatile("cp.async.cg.shared.global [%0], [%1], 16;" :: "r"(dst), "l"(src));
}

#define NEG_INF __int_as_float(0xff800000)

// smem layout (bytes)
#define XBYTES    (CH * PT * 4)             // 65536 per buffer
#define OFF_W2    (3 * XBYTES)              // 196608, ull[CH*8] = 16KB
#define OFF_ST    (OFF_W2 + CH * 8 * 8)     // 212992
#define STBYTES   (PT * SROW * 8)           // 4608 per stats buffer
#define OFF_W1    (OFF_ST + 2 * STBYTES)    // 222208
#define OFF_TW1   (OFF_W1 + CH * 4)         // 223232
#define SMEM_SZ   (OFF_TW1 + 128)           // 223360

__global__ void __launch_bounds__(TPB, 1)
cgblock_kernel(const float* __restrict__ x,
               const float* __restrict__ soft_w1,
               const float* __restrict__ soft_w2,
               const float* __restrict__ top_w1,
               const float* __restrict__ top_w2,
               const float* __restrict__ rr,
               float* __restrict__ out)
{
    extern __shared__ char sm[];
    ull*   s_w2  = (ull*)(sm + OFF_W2);
    float* s_w1  = (float*)(sm + OFF_W1);
    float* s_tw1 = (float*)(sm + OFF_TW1);

    const int tid  = threadIdx.x;
    const int warp = tid >> 5;
    const int lane = tid & 31;

    // ---- one-time weight prep: w2[o*8+g] = (rs*soft_w2[o,g], rt*top_w2[o,g]) ----
    {
        float r0 = __ldg(rr), r1 = __ldg(rr + 1);
        float rm = fmaxf(r0, r1);
        float e0 = __expf(r0 - rm), e1 = __expf(r1 - rm);
        float inv = __frcp_rn(e0 + e1);
        float w_top = e0 * inv, w_soft = e1 * inv;
        #pragma unroll
        for (int i = tid; i < CH * G; i += TPB) {
            int o = i >> 3, g = i & 7;
            s_w2[i] = pack2(w_soft * __ldg(soft_w2 + o * G + g),
                            w_top  * __ldg(top_w2  + o * G + g));
        }
        if (tid < G * CG) s_w1[tid] = __ldg(soft_w1 + tid);
        if (tid < G * 4)  s_tw1[tid] = __ldg(top_w1 + tid);
    }
    __syncthreads();

    const uint32_t xbuf[3] = { smem_u32(sm), smem_u32(sm + XBYTES), smem_u32(sm + 2 * XBYTES) };
    ull* s_st[2] = { (ull*)(sm + OFF_ST), (ull*)(sm + OFF_ST + STBYTES) };

    // prefetch mapping: warp covers 2 contiguous channel rows (16 x 16B each)
    const int ld_ch  = tid >> 4;          // 0..31
    const int ld_off = (tid & 15) * 16;   // byte offset in 256B row

    auto prefetch = [&](int t, int buf) {
        int p = t * PT, b = p >> 14, sp = p & (HWP - 1);
        const float* src0 = x + (size_t)b * CH * HWP + sp + (ld_off >> 2);
        uint32_t dst0 = xbuf[buf] + ld_ch * 256 + ld_off;
        #pragma unroll
        for (int cc = 0; cc < 8; cc++)
            cpa16(dst0 + cc * (32 * 256), src0 + (size_t)(cc * 32 + ld_ch) * HWP);
        asm volatile("cp.async.commit_group;" ::: "memory");
    };

    auto phase1 = [&](int buf, int sb) {
        const int g  = tid >> 6;          // 0..7
        const int px = tid & 63;          // 0..63
        const float* xr = (const float*)(size_t)0;   // placate; real below
        const float* xt = (const float*)(sm + (size_t)buf * XBYTES);
        xr = xt + (g * CG) * PT + px;
        float es = 0.f, ys = 0.f;
        float a0 = NEG_INF, b0 = NEG_INF, c0 = NEG_INF, d0 = NEG_INF;
        #pragma unroll 8
        for (int c = 0; c < CG; c++) {
            float v  = xr[c * PT];
            float w1 = s_w1[g * CG + c];
            float e = __expf(v); es += e; ys = fmaf(v * e, w1, ys);
            float f  = fminf(a0, v); a0 = fmaxf(a0, v);
            float h  = fminf(b0, f); b0 = fmaxf(b0, f);
            float i2 = fminf(c0, h); c0 = fmaxf(c0, h);
            d0 = fmaxf(d0, i2);
        }
        float k0 = s_tw1[g * 4 + 0], k1 = s_tw1[g * 4 + 1];
        float k2 = s_tw1[g * 4 + 2], k3 = s_tw1[g * 4 + 3];
        float sv = __fdividef(ys, es);
        float tv = fmaf(a0, k0, fmaf(b0, k1, fmaf(c0, k2, d0 * k3)));
        s_st[sb][px * SROW + g] = pack2(sv, tv);
    };

    auto phase2 = [&](int t, int buf, int sb) {
        ull st0[8], st1[8];
        const ull* ps = s_st[sb];
        #pragma unroll
        for (int g = 0; g < 8; g++) {
            st0[g] = ps[lane * SROW + g];
            st1[g] = ps[(lane + 32) * SROW + g];
        }
        const float* xt = (const float*)(sm + (size_t)buf * XBYTES);
        int p = t * PT, b = p >> 14, sp = p & (HWP - 1);
        float* ob = out + (size_t)b * CH * HWP + sp;
        #pragma unroll 4
        for (int i = 0; i < 16; i++) {
            int o = warp * 16 + i;
            float x0 = xt[o * PT + lane];
            float x1 = xt[o * PT + 32 + lane];
            ull acc0 = pack2(x0, 0.f);
            ull acc1 = pack2(x1, 0.f);
            const ulonglong2* wo = (const ulonglong2*)(s_w2 + o * 8);
            #pragma unroll
            for (int gg = 0; gg < 4; gg++) {
                ulonglong2 wv = wo[gg];
                fma2(acc0, st0[2 * gg],     wv.x);
                fma2(acc1, st1[2 * gg],     wv.x);
                fma2(acc0, st0[2 * gg + 1], wv.y);
                fma2(acc1, st1[2 * gg + 1], wv.y);
            }
            float lo, hi;
            unpack2(acc0, lo, hi);
            __stcs(ob + (size_t)o * HWP + lane, lo + hi);
            unpack2(acc1, lo, hi);
            __stcs(ob + (size_t)o * HWP + 32 + lane, lo + hi);
        }
    };

    // ---- prologue ----
    const int S  = gridDim.x;
    const int t0 = blockIdx.x;

    prefetch(t0, 0);
    bool has1 = (t0 + S) < NT;
    if (has1) {
        prefetch(t0 + S, 1);
        asm volatile("cp.async.wait_group 1;" ::: "memory");
    } else {
        asm volatile("cp.async.wait_group 0;" ::: "memory");
    }
    __syncthreads();
    phase1(0, 0);
    __syncthreads();

    // ---- main loop: phase1(t+S) overlaps phase2(t) between barriers ----
    int i = 0;
    for (int t = t0; t < NT; t += S, i++) {
        int tn  = t + S;
        int tnn = t + 2 * S;
        int bufc = i % 3, bufn = (i + 1) % 3, bufp = (i + 2) % 3;
        int sc = i & 1, sn = sc ^ 1;

        if (tnn < NT) prefetch(tnn, bufp);
        if (tn < NT) {
            if (tnn < NT) { asm volatile("cp.async.wait_group 1;" ::: "memory"); }
            else          { asm volatile("cp.async.wait_group 0;" ::: "memory"); }
            __syncthreads();            // tile tn visible
            phase1(bufn, sn);           // stats for tn (no barrier before phase2!)
        }
        phase2(t, bufc, sc);
        __syncthreads();                // stats(tn) done; bufc free for prefetch
    }
}

extern "C" void kernel_launch(void* const* d_in, const int* in_sizes, int n_in,
                              void* d_out, int out_size) {
    const float* x   = (const float*)d_in[0];
    const float* sw1 = (const float*)d_in[1];
    const float* sw2 = (const float*)d_in[2];
    const float* tw1 = (const float*)d_in[3];
    const float* tw2 = (const float*)d_in[4];
    const float* r   = (const float*)d_in[5];
    float* out = (float*)d_out;

    static int sms = 0;
    if (sms == 0) cudaDeviceGetAttribute(&sms, cudaDevAttrMultiProcessorCount, 0);

    static bool attr_set = false;
    if (!attr_set) {
        cudaFuncSetAttribute(cgblock_kernel,
                             cudaFuncAttributeMaxDynamicSharedMemorySize, SMEM_SZ);
        attr_set = true;
    }

    cgblock_kernel<<<sms, TPB, SMEM_SZ>>>(x, sw1, sw2, tw1, tw2, r, out);
}